// round 1
// baseline (speedup 1.0000x reference)
#include <cuda_runtime.h>

// Maxwell RNN cell: per-row linear recurrence over time.
//   a_t     = k * dt_t                      (k = E/eta = 0.5)
//   sig_t   = E_inf*eps_t + (eps_t - gamma_{t-1})        (E = 1.0)
//   gamma_t = (1 - a_t) * gamma_{t-1} + a_t * eps_t,  gamma_{-1} = 0
// Parallelized over T via affine composition: over a segment,
//   gamma_out = P * gamma_in + Q,  P = prod(1-a_t), Q = scan of recurrence from 0.

#define K_COEF 0.5f   // E_MOD / ETA
#define E_INF  1.5f

constexpr int B  = 4096;
constexpr int T  = 8192;
constexpr int S  = 64;         // segments along T
constexpr int L  = T / S;      // 128 timesteps per segment
constexpr int R  = 128;        // rows per block (= blockDim.x)
constexpr int CH = 32;         // chunk width in t
constexpr int CHP = 33;        // padded smem row stride (odd -> conflict-free compute)
constexpr int NV4 = (R * CH) / 4 / R;  // float4 loads per thread per array = 8

// Scratch (allocation-free rule: device globals)
__device__ float g_P[S * B];
__device__ float g_Q[S * B];
__device__ float g_gin[S * B];

// ---------------- pass 1: per (row, segment) compute (P, Q) ----------------
__global__ void __launch_bounds__(R, 6)
pass1_kernel(const float* __restrict__ eps, const float* __restrict__ dt) {
    __shared__ float se[R * CHP];
    __shared__ float sd[R * CHP];

    const int tid  = threadIdx.x;
    const int seg  = blockIdx.x;          // 0..S-1
    const int row0 = blockIdx.y * R;      // 0..B-R
    const int tbase = seg * L;

    float P = 1.0f, Q = 0.0f;

    for (int c0 = 0; c0 < L; c0 += CH) {
        __syncthreads();  // protect smem from previous chunk's readers
        // coalesced float4 load of [R x CH] tile for eps and dt
        #pragma unroll
        for (int i = 0; i < NV4; i++) {
            int lin = i * R + tid;          // 0..1023 float4 slots
            int r   = lin >> 3;             // row within tile
            int c4  = (lin & 7) * 4;        // column (multiple of 4)
            size_t gidx = (size_t)(row0 + r) * T + (tbase + c0 + c4);
            float4 ve = *reinterpret_cast<const float4*>(eps + gidx);
            float4 vd = *reinterpret_cast<const float4*>(dt  + gidx);
            int sb = r * CHP + c4;
            se[sb + 0] = ve.x; se[sb + 1] = ve.y; se[sb + 2] = ve.z; se[sb + 3] = ve.w;
            sd[sb + 0] = vd.x; sd[sb + 1] = vd.y; sd[sb + 2] = vd.z; sd[sb + 3] = vd.w;
        }
        __syncthreads();
        // each thread folds its own row sequentially (conflict-free: stride 33)
        #pragma unroll
        for (int c = 0; c < CH; c++) {
            float e  = se[tid * CHP + c];
            float d  = sd[tid * CHP + c];
            float ad = K_COEF * d;
            float A  = 1.0f - ad;
            P = P * A;
            Q = fmaf(A, Q, ad * e);
        }
    }
    const int row = row0 + tid;
    g_P[seg * B + row] = P;
    g_Q[seg * B + row] = Q;
}

// -------- pass 2: serial scan over segments, per row (fully coalesced) -----
__global__ void pass2_kernel() {
    const int row = blockIdx.x * blockDim.x + threadIdx.x;
    float g = 0.0f;
    #pragma unroll
    for (int s = 0; s < S; s++) {
        g_gin[s * B + row] = g;
        g = fmaf(g_P[s * B + row], g, g_Q[s * B + row]);
    }
}

// ------- pass 3: replay recurrence with correct gamma_in, emit sigma -------
__global__ void __launch_bounds__(R, 6)
pass3_kernel(const float* __restrict__ eps, const float* __restrict__ dt,
             float* __restrict__ out) {
    __shared__ float se[R * CHP];
    __shared__ float sd[R * CHP];

    const int tid  = threadIdx.x;
    const int seg  = blockIdx.x;
    const int row0 = blockIdx.y * R;
    const int tbase = seg * L;

    float g = g_gin[seg * B + (row0 + tid)];

    for (int c0 = 0; c0 < L; c0 += CH) {
        // load tile
        #pragma unroll
        for (int i = 0; i < NV4; i++) {
            int lin = i * R + tid;
            int r   = lin >> 3;
            int c4  = (lin & 7) * 4;
            size_t gidx = (size_t)(row0 + r) * T + (tbase + c0 + c4);
            float4 ve = *reinterpret_cast<const float4*>(eps + gidx);
            float4 vd = *reinterpret_cast<const float4*>(dt  + gidx);
            int sb = r * CHP + c4;
            se[sb + 0] = ve.x; se[sb + 1] = ve.y; se[sb + 2] = ve.z; se[sb + 3] = ve.w;
            sd[sb + 0] = vd.x; sd[sb + 1] = vd.y; sd[sb + 2] = vd.z; sd[sb + 3] = vd.w;
        }
        __syncthreads();
        // compute sigma in place (overwrite eps tile)
        #pragma unroll
        for (int c = 0; c < CH; c++) {
            float e    = se[tid * CHP + c];
            float d    = sd[tid * CHP + c];
            float diff = e - g;
            float sig  = fmaf(E_INF, e, diff);          // E_inf*e + 1.0*(e - g)
            g = fmaf(K_COEF * d, diff, g);              // g += dt*k*(e - g)
            se[tid * CHP + c] = sig;
        }
        __syncthreads();
        // coalesced float4 store
        #pragma unroll
        for (int i = 0; i < NV4; i++) {
            int lin = i * R + tid;
            int r   = lin >> 3;
            int c4  = (lin & 7) * 4;
            int sb  = r * CHP + c4;
            float4 v;
            v.x = se[sb + 0]; v.y = se[sb + 1]; v.z = se[sb + 2]; v.w = se[sb + 3];
            size_t gidx = (size_t)(row0 + r) * T + (tbase + c0 + c4);
            *reinterpret_cast<float4*>(out + gidx) = v;
        }
        __syncthreads();  // smem reused by next chunk's loads
    }
}

extern "C" void kernel_launch(void* const* d_in, const int* in_sizes, int n_in,
                              void* d_out, int out_size) {
    const float* eps = (const float*)d_in[0];
    const float* dt  = (const float*)d_in[1];
    float* out = (float*)d_out;

    dim3 grid(S, B / R);
    pass1_kernel<<<grid, R>>>(eps, dt);
    pass2_kernel<<<B / 256, 256>>>();
    pass3_kernel<<<grid, R>>>(eps, dt, out);
}

// round 3
// speedup vs baseline: 1.4395x; 1.4395x over previous
#include <cuda_runtime.h>

// Maxwell RNN: per-row linear recurrence, single-pass decoupled lookback.
//   A_t = 1 - 0.5*dt_t
//   gamma_t = A_t*gamma_{t-1} + (0.5*dt_t)*eps_t, gamma_{-1}=0
//   sig_t   = 2.5*eps_t - gamma_{t-1}
// Over a segment, gamma is affine in gamma_in: gamma = P*g_in + Q, and
//   sig_t = (2.5*e_t - Qp_t) - Pp_t * g_in   (Pp,Qp = prefix before step t)

constexpr int Bn = 4096;
constexpr int Tn = 8192;
constexpr int R  = 128;           // rows per block = threads
constexpr int L  = 64;            // timesteps per segment
constexpr int S  = Tn / L;        // 128 segments
constexpr int G  = Bn / R;        // 32 row groups
constexpr int NBLK = S * G;       // 4096 blocks
constexpr int STRIDE = L + 1;     // 65: conflict-free scalar smem access
constexpr int V4 = (R * L / 4) / R;   // 16 float4 iters per thread per array

// Scratch (no allocations allowed)
__device__ float    g_aggP[NBLK * R];
__device__ float    g_aggQ[NBLK * R];
__device__ float    g_pref[NBLK * R];
__device__ int      g_flag[NBLK];
__device__ unsigned g_ticket;

__global__ void reset_kernel() {
    int i = blockIdx.x * blockDim.x + threadIdx.x;
    if (i < NBLK) g_flag[i] = 0;
    if (i == 0)  g_ticket = 0;
}

__global__ void __launch_bounds__(R)
maxwell_scan_kernel(const float* __restrict__ eps, const float* __restrict__ dt,
                    float* __restrict__ out) {
    extern __shared__ float smem[];
    float* sE = smem;                 // eps tile, later C_t
    float* sD = smem + R * STRIDE;    // dt tile, later Pp_t

    __shared__ unsigned s_vid;
    __shared__ int s_flag;

    const int tid = threadIdx.x;

    // Ticket: virtual block id in arrival order (deadlock-free lookback)
    if (tid == 0) s_vid = atomicAdd(&g_ticket, 1u);
    __syncthreads();
    const int vid = (int)s_vid;
    const int rg  = vid % G;          // row group
    const int seg = vid / G;          // segment along T
    const int id  = vid;              // flag/value index (seg-major: pred = id - G)

    // ---- load tile (coalesced float4; scalar smem stores to padded layout) ----
    #pragma unroll
    for (int i = 0; i < V4; i++) {
        int lin = i * R + tid;                 // 0..2047
        int r   = lin >> 4;                    // 16 float4 per row
        int c4  = (lin & 15) << 2;
        size_t gi = (size_t)(rg * R + r) * Tn + (size_t)seg * L + c4;
        float4 ve = *reinterpret_cast<const float4*>(eps + gi);
        float4 vd = *reinterpret_cast<const float4*>(dt  + gi);
        int sb = r * STRIDE + c4;
        sE[sb + 0] = ve.x; sE[sb + 1] = ve.y; sE[sb + 2] = ve.z; sE[sb + 3] = ve.w;
        sD[sb + 0] = vd.x; sD[sb + 1] = vd.y; sD[sb + 2] = vd.z; sD[sb + 3] = vd.w;
    }
    __syncthreads();

    // ---- local pass: running prefix (P,Q); rewrite tile as (C_t, Pp_t) ----
    float P = 1.0f, Q = 0.0f;
    #pragma unroll
    for (int c = 0; c < L; c++) {
        int sb = tid * STRIDE + c;
        float e = sE[sb];
        float d = sD[sb];
        sD[sb] = P;                    // Pp_t (prefix before step t)
        sE[sb] = fmaf(2.5f, e, -Q);    // C_t = 2.5*e_t - Qp_t
        float ad = 0.5f * d;
        float A  = 1.0f - ad;
        P = P * A;
        Q = fmaf(A, Q, ad * e);
    }

    float gin = 0.0f;

    if (seg == 0) {
        // First partition: publish inclusive prefix ONLY (flag 0 -> 2).
        // Never publishes flag=1, so lookback can never step past segment 0.
        g_pref[id * R + tid] = Q;     // gamma at end of segment (gin = 0)
        __threadfence();
        __syncthreads();
        if (tid == 0) atomicExch(&g_flag[id], 2);
    } else {
        // ---- publish aggregate ----
        g_aggP[id * R + tid] = P;
        g_aggQ[id * R + tid] = Q;
        __threadfence();
        __syncthreads();
        if (tid == 0) atomicExch(&g_flag[id], 1);

        // ---- lookback for gamma_in ----
        float hP = 1.0f, hQ = 0.0f;
        int p = id - G;
        bool done = false;
        while (!done) {
            if (tid == 0) {
                int f;
                do { f = atomicAdd(&g_flag[p], 0); } while (f == 0);
                s_flag = f;
            }
            __syncthreads();           // orders data loads after flag observation
            int f = s_flag;
            if (f == 2) {
                float gp = __ldcg(&g_pref[p * R + tid]);
                gin = fmaf(hP, gp, hQ);
                done = true;
            } else {
                float Pp = __ldcg(&g_aggP[p * R + tid]);
                float Qp = __ldcg(&g_aggQ[p * R + tid]);
                hQ = fmaf(hP, Qp, hQ);
                hP = hP * Pp;
                p -= G;                 // safe: seg 0 only ever shows flag 0 or 2
            }
            __syncthreads();            // protect s_flag reuse
        }

        // ---- publish inclusive prefix (gamma at end of this segment) ----
        g_pref[id * R + tid] = fmaf(P, gin, Q);
        __threadfence();
        __syncthreads();
        if (tid == 0) atomicExch(&g_flag[id], 2);
    }

    // ---- fixup: sig_t = C_t - Pp_t * gin ----
    #pragma unroll
    for (int c = 0; c < L; c++) {
        int sb = tid * STRIDE + c;
        sE[sb] = fmaf(-sD[sb], gin, sE[sb]);
    }
    __syncthreads();

    // ---- coalesced float4 store ----
    #pragma unroll
    for (int i = 0; i < V4; i++) {
        int lin = i * R + tid;
        int r   = lin >> 4;
        int c4  = (lin & 15) << 2;
        int sb  = r * STRIDE + c4;
        float4 v;
        v.x = sE[sb + 0]; v.y = sE[sb + 1]; v.z = sE[sb + 2]; v.w = sE[sb + 3];
        size_t gi = (size_t)(rg * R + r) * Tn + (size_t)seg * L + c4;
        *reinterpret_cast<float4*>(out + gi) = v;
    }
}

extern "C" void kernel_launch(void* const* d_in, const int* in_sizes, int n_in,
                              void* d_out, int out_size) {
    const float* eps = (const float*)d_in[0];
    const float* dt  = (const float*)d_in[1];
    float* out = (float*)d_out;

    constexpr int SMEM = 2 * R * STRIDE * sizeof(float);   // 66,560 B
    cudaFuncSetAttribute(maxwell_scan_kernel,
                         cudaFuncAttributeMaxDynamicSharedMemorySize, SMEM);

    reset_kernel<<<(NBLK + 255) / 256, 256>>>();
    maxwell_scan_kernel<<<NBLK, R, SMEM>>>(eps, dt, out);
}

// round 4
// speedup vs baseline: 1.5671x; 1.0886x over previous
#include <cuda_runtime.h>

// Maxwell RNN: per-row linear recurrence, register-resident single-pass
// decoupled lookback with scalar per-block state.
//   gamma_t = (1 - 0.5*dt)*gamma_{t-1} + 0.5*dt*eps_t,  gamma_{-1}=0
//   sig_t   = 2.5*eps_t - gamma_{t-1}
// Affine rep f(x)=P*x+Q composes: later∘earlier = (Pl*Pe, Pl*Qe + Ql).

constexpr int Bn  = 4096;
constexpr int Tn  = 8192;
constexpr int TPB = 256;           // threads per block
constexpr int EPT = 4;             // elements per thread (one float4)
constexpr int SEG = TPB * EPT;     // 1024 timesteps per block
constexpr int S   = Tn / SEG;      // 8 segments per row
constexpr int NB  = Bn * S;        // 32768 blocks

// Scratch (allocation-free rule: device globals)
__device__ float    g_aggP[NB];
__device__ float    g_aggQ[NB];
__device__ float    g_pref[NB];
__device__ int      g_flag[NB];
__device__ unsigned g_ticket;

__global__ void reset_kernel() {
    int i = blockIdx.x * blockDim.x + threadIdx.x;
    if (i < NB) g_flag[i] = 0;
    if (i == 0) g_ticket = 0;
}

__global__ void __launch_bounds__(TPB)
maxwell_scan_kernel(const float* __restrict__ eps, const float* __restrict__ dt,
                    float* __restrict__ out) {
    __shared__ float sWP[TPB / 32];     // warp aggregates -> exclusive prefixes
    __shared__ float sWQ[TPB / 32];
    __shared__ float s_gin;
    __shared__ unsigned s_vid;

    const int tid  = threadIdx.x;
    const int lane = tid & 31;
    const int wid  = tid >> 5;

    // Ticket = virtual block id in scheduling order (deadlock-free lookback)
    if (tid == 0) s_vid = atomicAdd(&g_ticket, 1u);
    __syncthreads();
    const int vid = (int)s_vid;
    const int seg = vid >> 12;          // vid / Bn  (seg-major: seg 0 first)
    const int row = vid & (Bn - 1);

    const size_t base = (size_t)row * Tn + (size_t)seg * SEG + tid * EPT;
    const float4 e4 = *reinterpret_cast<const float4*>(eps + base);
    const float4 d4 = *reinterpret_cast<const float4*>(dt  + base);
    const float ee[4] = {e4.x, e4.y, e4.z, e4.w};
    const float dd[4] = {d4.x, d4.y, d4.z, d4.w};

    // Thread-local affine prefix; retain C_j, Pp_j for deferred fixup.
    float P = 1.0f, Q = 0.0f;
    float C[4], Pp[4];
    #pragma unroll
    for (int j = 0; j < 4; j++) {
        Pp[j] = P;
        C[j]  = fmaf(2.5f, ee[j], -Q);      // sig_j = C_j - Pp_j * g_thread_start
        float ad = 0.5f * dd[j];
        float A  = 1.0f - ad;
        P = P * A;
        Q = fmaf(A, Q, ad * ee[j]);
    }

    // Warp-inclusive affine scan (5 shuffle steps)
    #pragma unroll
    for (int off = 1; off < 32; off <<= 1) {
        float Pu = __shfl_up_sync(0xFFFFFFFFu, P, off);
        float Qu = __shfl_up_sync(0xFFFFFFFFu, Q, off);
        if (lane >= off) { Q = fmaf(P, Qu, Q); P *= Pu; }
    }
    // Lane-exclusive prefix for this thread
    float LPe = __shfl_up_sync(0xFFFFFFFFu, P, 1);
    float LQe = __shfl_up_sync(0xFFFFFFFFu, Q, 1);
    if (lane == 0) { LPe = 1.0f; LQe = 0.0f; }

    if (lane == 31) { sWP[wid] = P; sWQ[wid] = Q; }   // warp-inclusive aggregates
    __syncthreads();

    // Warp 0 lanes 0..7: scan the 8 warp aggregates; publish + lookback.
    if (wid == 0 && lane < 8) {
        float p = sWP[lane], q = sWQ[lane];
        #pragma unroll
        for (int off = 1; off < 8; off <<= 1) {
            float pu = __shfl_up_sync(0xFFu, p, off);
            float qu = __shfl_up_sync(0xFFu, q, off);
            if (lane >= off) { q = fmaf(p, qu, q); p *= pu; }
        }
        float pe = __shfl_up_sync(0xFFu, p, 1);
        float qe = __shfl_up_sync(0xFFu, q, 1);
        if (lane == 0) { pe = 1.0f; qe = 0.0f; }
        sWP[lane] = pe;                   // overwrite with warp-exclusive prefixes
        sWQ[lane] = qe;
        float BP = __shfl_sync(0xFFu, p, 7);   // block aggregate
        float BQ = __shfl_sync(0xFFu, q, 7);

        if (lane == 0) {
            float gin = 0.0f;
            if (seg == 0) {
                // First partition publishes prefix ONLY (never flag=1).
                g_pref[vid] = BQ;
                __threadfence();
                atomicExch(&g_flag[vid], 2);
            } else {
                g_aggP[vid] = BP;
                g_aggQ[vid] = BQ;
                __threadfence();
                atomicExch(&g_flag[vid], 1);

                float hP = 1.0f, hQ = 0.0f;
                int p2 = vid - Bn;
                for (;;) {
                    int f;
                    do { f = atomicAdd(&g_flag[p2], 0); } while (f == 0);
                    __threadfence();
                    if (f == 2) {
                        float gp = __ldcg(&g_pref[p2]);
                        gin = fmaf(hP, gp, hQ);
                        break;
                    }
                    float Pq = __ldcg(&g_aggP[p2]);
                    float Qq = __ldcg(&g_aggQ[p2]);
                    hQ = fmaf(hP, Qq, hQ);
                    hP = hP * Pq;
                    p2 -= Bn;             // safe: seg 0 only shows flag 0 or 2
                }
                g_pref[vid] = fmaf(BP, gin, BQ);
                __threadfence();
                atomicExch(&g_flag[vid], 2);
            }
            s_gin = gin;
        }
    }
    __syncthreads();

    // Compose: gin -> warp start -> thread start; fixup & coalesced store.
    const float gin = s_gin;
    const float gw  = fmaf(sWP[wid], gin, sWQ[wid]);
    const float gt  = fmaf(LPe, gw, LQe);

    float4 o;
    o.x = fmaf(-Pp[0], gt, C[0]);
    o.y = fmaf(-Pp[1], gt, C[1]);
    o.z = fmaf(-Pp[2], gt, C[2]);
    o.w = fmaf(-Pp[3], gt, C[3]);
    *reinterpret_cast<float4*>(out + base) = o;
}

extern "C" void kernel_launch(void* const* d_in, const int* in_sizes, int n_in,
                              void* d_out, int out_size) {
    const float* eps = (const float*)d_in[0];
    const float* dt  = (const float*)d_in[1];
    float* out = (float*)d_out;

    reset_kernel<<<(NB + 255) / 256, 256>>>();
    maxwell_scan_kernel<<<NB, TPB>>>(eps, dt, out);
}

// round 5
// speedup vs baseline: 2.5753x; 1.6434x over previous
#include <cuda_runtime.h>

// Maxwell RNN: per-row linear recurrence. One block owns one full row
// (T = 8192 = 512 threads x 16 elements), so there is NO inter-block
// dependency: no lookback, no atomics, no flags, single kernel launch.
//
//   gamma_t = (1 - 0.5*dt_t)*gamma_{t-1} + 0.5*dt_t*eps_t,  gamma_{-1} = 0
//   sig_t   = 1.5*eps_t + (eps_t - gamma_{t-1})
//
// Affine rep f(x) = P*x + Q composes; block scan gives each thread its
// starting gamma, then the recurrence is replayed in registers.

constexpr int Bn  = 4096;
constexpr int Tn  = 8192;
constexpr int TPB = 512;
constexpr int EPT = 16;                 // elements per thread
constexpr int NW  = TPB / 32;           // 16 warps
static_assert(TPB * EPT == Tn, "one block = one row");

__global__ void __launch_bounds__(TPB)
maxwell_row_kernel(const float* __restrict__ eps, const float* __restrict__ dt,
                   float* __restrict__ out) {
    __shared__ float sWP[NW];           // warp aggregates -> exclusive prefixes
    __shared__ float sWQ[NW];

    const int tid  = threadIdx.x;
    const int lane = tid & 31;
    const int wid  = tid >> 5;

    const size_t base = (size_t)blockIdx.x * Tn + (size_t)tid * EPT;

    // ---- load 16 eps + 16 dt as 8 independent float4s (max MLP) ----
    float4 ev[4], dv[4];
    #pragma unroll
    for (int v = 0; v < 4; v++) {
        ev[v] = *reinterpret_cast<const float4*>(eps + base + v * 4);
        dv[v] = *reinterpret_cast<const float4*>(dt  + base + v * 4);
    }
    float ee[EPT], dd[EPT];
    #pragma unroll
    for (int v = 0; v < 4; v++) {
        ee[v*4+0] = ev[v].x; ee[v*4+1] = ev[v].y; ee[v*4+2] = ev[v].z; ee[v*4+3] = ev[v].w;
        dd[v*4+0] = dv[v].x; dd[v*4+1] = dv[v].y; dd[v*4+2] = dv[v].z; dd[v*4+3] = dv[v].w;
    }

    // ---- thread-local affine fold: gamma_out = P*gamma_in + Q ----
    float P = 1.0f, Q = 0.0f;
    #pragma unroll
    for (int j = 0; j < EPT; j++) {
        float ad = 0.5f * dd[j];
        float A  = 1.0f - ad;
        Q = fmaf(A, Q, ad * ee[j]);
        P = P * A;
    }

    // ---- warp-inclusive affine scan (5 shuffle steps) ----
    #pragma unroll
    for (int off = 1; off < 32; off <<= 1) {
        float Pu = __shfl_up_sync(0xFFFFFFFFu, P, off);
        float Qu = __shfl_up_sync(0xFFFFFFFFu, Q, off);
        if (lane >= off) { Q = fmaf(P, Qu, Q); P *= Pu; }
    }
    // thread-exclusive prefix within warp
    float LPe = __shfl_up_sync(0xFFFFFFFFu, P, 1);
    float LQe = __shfl_up_sync(0xFFFFFFFFu, Q, 1);
    if (lane == 0) { LPe = 1.0f; LQe = 0.0f; }

    if (lane == 31) { sWP[wid] = P; sWQ[wid] = Q; }
    __syncthreads();

    // ---- warp 0 scans the 16 warp aggregates -> warp-exclusive prefixes ----
    if (wid == 0 && lane < NW) {
        float p = sWP[lane], q = sWQ[lane];
        #pragma unroll
        for (int off = 1; off < NW; off <<= 1) {
            float pu = __shfl_up_sync(0xFFFFu, p, off);
            float qu = __shfl_up_sync(0xFFFFu, q, off);
            if (lane >= off) { q = fmaf(p, qu, q); p *= pu; }
        }
        float pe = __shfl_up_sync(0xFFFFu, p, 1);
        float qe = __shfl_up_sync(0xFFFFu, q, 1);
        if (lane == 0) { pe = 1.0f; qe = 0.0f; }
        sWP[lane] = pe;
        sWQ[lane] = qe;
    }
    __syncthreads();

    // gamma at block start = 0, so warp-start gamma = warp-exclusive Q.
    const float gw = sWQ[wid];
    float g = fmaf(LPe, gw, LQe);       // thread-start gamma

    // ---- replay recurrence with known start state; emit sigma ----
    float4 ov[4];
    #pragma unroll
    for (int v = 0; v < 4; v++) {
        float s[4];
        #pragma unroll
        for (int u = 0; u < 4; u++) {
            int j = v * 4 + u;
            float diff = ee[j] - g;
            s[u] = fmaf(1.5f, ee[j], diff);          // sig = 1.5*e + (e - g)
            g = fmaf(0.5f * dd[j], diff, g);         // g  += 0.5*dt*(e - g)
        }
        ov[v] = make_float4(s[0], s[1], s[2], s[3]);
    }
    #pragma unroll
    for (int v = 0; v < 4; v++) {
        *reinterpret_cast<float4*>(out + base + v * 4) = ov[v];
    }
}

extern "C" void kernel_launch(void* const* d_in, const int* in_sizes, int n_in,
                              void* d_out, int out_size) {
    const float* eps = (const float*)d_in[0];
    const float* dt  = (const float*)d_in[1];
    float* out = (float*)d_out;

    maxwell_row_kernel<<<Bn, TPB>>>(eps, dt, out);
}